// round 1
// baseline (speedup 1.0000x reference)
#include <cuda_runtime.h>
#include <math.h>

// Problem dims
#define B_ 32
#define J_ 1024
#define D_ 192
#define E_ 384
#define N_ 16
#define M_ (B_*J_)   // 32768 rows

// ---------------- scratch (static __device__, no runtime alloc) ----------------
__device__ __align__(16) float g_t   [M_*D_];
__device__ __align__(16) float g_x   [M_*E_];
__device__ __align__(16) float g_gate[M_*E_];
__device__ __align__(16) float g_xcf [M_*E_];
__device__ __align__(16) float g_xcb [M_*E_];
__device__ __align__(16) float g_Pf  [M_*64];
__device__ __align__(16) float g_Pb  [M_*64];
__device__ __align__(16) float g_Ab  [2*M_*N_];
__device__ __align__(16) float g_Bu  [2*M_*N_];
__device__ __align__(16) float g_Ct  [2*M_*N_];
__device__ __align__(16) float g_S   [2*M_*N_];
__device__ __align__(16) float g_Yg  [M_*E_];
__device__ __align__(16) float g_Wf  [E_*64];
__device__ __align__(16) float g_Wb  [E_*64];
__device__ __align__(16) float g_bf  [64];
__device__ __align__(16) float g_bb  [64];
__device__ __align__(16) float g_Aneg[N_];

__device__ __forceinline__ float softplusf(float x) {
    return x > 20.f ? x : log1pf(expf(x));
}

// ---------------- weight packing: [WB|WC|WD|Wi] -> (E,64); A = -softplus(A_log) ----
__global__ void prep_pack(const float* __restrict__ WBf, const float* __restrict__ WCf,
                          const float* __restrict__ WDf, const float* __restrict__ WBb,
                          const float* __restrict__ WCb, const float* __restrict__ WDb,
                          const float* __restrict__ Wi,
                          const float* __restrict__ bBf, const float* __restrict__ bCf,
                          const float* __restrict__ bDf, const float* __restrict__ bBb,
                          const float* __restrict__ bCb, const float* __restrict__ bDb,
                          const float* __restrict__ bi, const float* __restrict__ A_log) {
    int i = blockIdx.x * blockDim.x + threadIdx.x;
    if (i < E_*64) {
        int e = i >> 6, c = i & 63;
        const float* sf = (c < 16) ? WBf : (c < 32) ? WCf : (c < 48) ? WDf : Wi;
        const float* sb = (c < 16) ? WBb : (c < 32) ? WCb : (c < 48) ? WDb : Wi;
        g_Wf[i] = sf[e*N_ + (c & 15)];
        g_Wb[i] = sb[e*N_ + (c & 15)];
    }
    if (i < 64) {
        const float* sf = (i < 16) ? bBf : (i < 32) ? bCf : (i < 48) ? bDf : bi;
        const float* sb = (i < 16) ? bBb : (i < 32) ? bCb : (i < 48) ? bDb : bi;
        g_bf[i] = sf[i & 15];
        g_bb[i] = sb[i & 15];
    }
    if (i < N_) g_Aneg[i] = -softplusf(A_log[i]);
}

// ---------------- LayerNorm: one warp per row (D=192 = 6 per lane) ----------------
__global__ void ln_kernel(const float* __restrict__ tok, const float* __restrict__ gw,
                          const float* __restrict__ gb) {
    int warp = (blockIdx.x * blockDim.x + threadIdx.x) >> 5;
    int lane = threadIdx.x & 31;
    if (warp >= M_) return;
    const float* r = tok + (size_t)warp * D_;
    float v[6];
    float s = 0.f;
#pragma unroll
    for (int i = 0; i < 6; i++) { v[i] = r[lane + i*32]; s += v[i]; }
#pragma unroll
    for (int o = 16; o; o >>= 1) s += __shfl_xor_sync(0xffffffffu, s, o);
    float mu = s * (1.f / D_);
    float q = 0.f;
#pragma unroll
    for (int i = 0; i < 6; i++) { float d = v[i] - mu; q += d * d; }
#pragma unroll
    for (int o = 16; o; o >>= 1) q += __shfl_xor_sync(0xffffffffu, q, o);
    float rs = rsqrtf(q * (1.f / D_) + 1e-5f);
    float* o = g_t + (size_t)warp * D_;
#pragma unroll
    for (int i = 0; i < 6; i++) {
        int c = lane + i*32;
        o[c] = (v[i] - mu) * rs * gw[c] + gb[c];
    }
}

// ---------------- tiled fp32 GEMM, BM=BN=64, BK=16, 256 thr, 4x4 microtile ---------
// C[M,ND] = (A (+A2)) [M,KD] @ W[KD,ND], epilogues fused.
enum { EPI_PLAIN = 0, EPI_GATE = 1, EPI_MUL = 2, EPI_ADD = 3 };

template <int KD, int ND, int EPI>
__global__ void __launch_bounds__(256) sgemm(const float* __restrict__ A,
                                             const float* __restrict__ A2,
                                             const float* __restrict__ W,
                                             const float* __restrict__ bias,
                                             float bscale,
                                             const float* __restrict__ aux,
                                             float* __restrict__ C) {
    __shared__ float As[16][68];   // transposed A tile (pad 4 -> 16B-aligned rows)
    __shared__ float Ws[16][64];
    int tid = threadIdx.x;
    int tx = tid & 15, ty = tid >> 4;
    int row0 = blockIdx.y * 64, col0 = blockIdx.x * 64;
    int lm = tid >> 2, lk = (tid & 3) * 4;   // A-tile loader: row lm, k-quad lk
    int wk = tid >> 4, wn = (tid & 15) * 4;  // W-tile loader
    float acc[4][4] = {};
    for (int k0 = 0; k0 < KD; k0 += 16) {
        float4 av = *(const float4*)(A + (size_t)(row0 + lm) * KD + k0 + lk);
        if (A2) {
            float4 a2 = *(const float4*)(A2 + (size_t)(row0 + lm) * KD + k0 + lk);
            av.x += a2.x; av.y += a2.y; av.z += a2.z; av.w += a2.w;
        }
        float4 wv = *(const float4*)(W + (size_t)(k0 + wk) * ND + col0 + wn);
        __syncthreads();
        As[lk + 0][lm] = av.x; As[lk + 1][lm] = av.y;
        As[lk + 2][lm] = av.z; As[lk + 3][lm] = av.w;
        *(float4*)&Ws[wk][wn] = wv;
        __syncthreads();
#pragma unroll
        for (int kk = 0; kk < 16; kk++) {
            float a[4], w[4];
            *(float4*)a = *(const float4*)&As[kk][ty * 4];
            *(float4*)w = *(const float4*)&Ws[kk][tx * 4];
#pragma unroll
            for (int i = 0; i < 4; i++)
#pragma unroll
                for (int j = 0; j < 4; j++)
                    acc[i][j] = fmaf(a[i], w[j], acc[i][j]);
        }
    }
    float4 bv = *(const float4*)(bias + col0 + tx * 4);
    const float* bp = &bv.x;
#pragma unroll
    for (int i = 0; i < 4; i++) {
        int row = row0 + ty * 4 + i;
        size_t co = (size_t)row * ND + col0 + tx * 4;
        float4 xv;
        if (EPI == EPI_MUL || EPI == EPI_ADD) xv = *(const float4*)(aux + co);
        float o[4];
#pragma unroll
        for (int j = 0; j < 4; j++) {
            float v = acc[i][j] + bscale * bp[j];
            if (EPI == EPI_GATE) {
                float sg = 1.f / (1.f + __expf(-v));      // sigmoid(z)
                float si = v * sg;                        // silu(z)
                v = 1.f / (1.f + __expf(-si));            // sigmoid(silu(z))
            } else if (EPI == EPI_MUL) {
                v *= (&xv.x)[j];
            } else if (EPI == EPI_ADD) {
                v += (&xv.x)[j];
            }
            o[j] = v;
        }
        *(float4*)(C + co) = *(float4*)o;
    }
}

// ---------------- depthwise conv K=3, fwd + (reversed-kernel) bwd -----------------
__global__ void conv_kernel(const float* __restrict__ cwf, const float* __restrict__ cbf,
                            const float* __restrict__ cwb, const float* __restrict__ cbb) {
    int idx = blockIdx.x * blockDim.x + threadIdx.x;
    if (idx >= M_ * E_) return;
    int bj = idx / E_;
    int e  = idx - bj * E_;
    int j  = bj & (J_ - 1);
    float x0 = g_x[idx];
    float xm = (j > 0)      ? g_x[idx - E_] : 0.f;
    float xp = (j < J_ - 1) ? g_x[idx + E_] : 0.f;
    float f0 = cwf[e*3], f1 = cwf[e*3+1], f2 = cwf[e*3+2];
    g_xcf[idx] = fmaf(f0, xm, fmaf(f1, x0, fmaf(f2, xp, cbf[e])));
    // backward pass in original coordinates == reversed kernel
    float b0 = cwb[e*3], b1 = cwb[e*3+1], b2 = cwb[e*3+2];
    g_xcb[idx] = fmaf(b0, xp, fmaf(b1, x0, fmaf(b2, xm, cbb[e])));
}

// ---------------- ZOH discretization from packed projections ----------------------
__global__ void ssm_prep() {
    int i = blockIdx.x * blockDim.x + threadIdx.x;
    if (i >= 2 * M_ * N_) return;
    int dir = i / (M_ * N_);
    int r   = i - dir * (M_ * N_);
    int n   = r & 15;
    int bj  = r >> 4;
    const float* P = dir ? g_Pb : g_Pf;
    float Bt = P[bj*64 + n];
    float Ct = P[bj*64 + 16 + n];
    float Dr = P[bj*64 + 32 + n];
    float u  = P[bj*64 + 48 + n];
    float Dt = softplusf(Dr);
    float Aa = g_Aneg[n];
    float ab = __expf(Dt * Aa);
    float bbar = (ab - 1.f) / (Aa + 1e-6f) * Bt;
    g_Ab[i] = ab;
    g_Bu[i] = bbar * u;
    g_Ct[i] = Ct;
}

// ---------------- sequential scan: one warp per (dir, b); lanes = n ---------------
__global__ void scan_kernel() {
    int wg   = blockIdx.x;          // 64 blocks of 32 threads
    int lane = threadIdx.x;
    if (lane >= N_) return;
    int dir = wg & 1, b = wg >> 1;
    int base = dir * M_ * N_ + b * J_ * N_ + lane;
    float h = 0.f;
    if (dir == 0) {
#pragma unroll 4
        for (int j = 0; j < J_; j++) {
            int idx = base + j * N_;
            h = fmaf(g_Ab[idx], h, g_Bu[idx]);
            g_S[idx] = h * g_Ct[idx];
        }
    } else {
#pragma unroll 4
        for (int j = J_ - 1; j >= 0; j--) {
            int idx = base + j * N_;
            h = fmaf(g_Ab[idx], h, g_Bu[idx]);
            g_S[idx] = h * g_Ct[idx];
        }
    }
}

// ---------------- launch ----------------------------------------------------------
extern "C" void kernel_launch(void* const* d_in, const int* in_sizes, int n_in,
                              void* d_out, int out_size) {
    const float* tokens  = (const float*)d_in[0];
    const float* norm_g  = (const float*)d_in[1];
    const float* norm_b  = (const float*)d_in[2];
    const float* Wx      = (const float*)d_in[3];
    const float* bx      = (const float*)d_in[4];
    const float* Wz      = (const float*)d_in[5];
    const float* bz      = (const float*)d_in[6];
    const float* convf_w = (const float*)d_in[7];
    const float* convf_b = (const float*)d_in[8];
    const float* convb_w = (const float*)d_in[9];
    const float* convb_b = (const float*)d_in[10];
    const float* WBf = (const float*)d_in[11];
    const float* bBf = (const float*)d_in[12];
    const float* WCf = (const float*)d_in[13];
    const float* bCf = (const float*)d_in[14];
    const float* WDf = (const float*)d_in[15];
    const float* bDf = (const float*)d_in[16];
    const float* WBb = (const float*)d_in[17];
    const float* bBb = (const float*)d_in[18];
    const float* WCb = (const float*)d_in[19];
    const float* bCb = (const float*)d_in[20];
    const float* WDb = (const float*)d_in[21];
    const float* bDb = (const float*)d_in[22];
    const float* A_log = (const float*)d_in[23];
    const float* Wi  = (const float*)d_in[24];
    const float* bi  = (const float*)d_in[25];
    const float* Wr  = (const float*)d_in[26];
    const float* br  = (const float*)d_in[27];
    const float* Wo  = (const float*)d_in[28];
    const float* bo  = (const float*)d_in[29];

    float *p_t, *p_x, *p_gate, *p_xcf, *p_xcb, *p_Wf, *p_Wb, *p_bf, *p_bb,
          *p_Pf, *p_Pb, *p_S, *p_Yg;
    cudaGetSymbolAddress((void**)&p_t,    g_t);
    cudaGetSymbolAddress((void**)&p_x,    g_x);
    cudaGetSymbolAddress((void**)&p_gate, g_gate);
    cudaGetSymbolAddress((void**)&p_xcf,  g_xcf);
    cudaGetSymbolAddress((void**)&p_xcb,  g_xcb);
    cudaGetSymbolAddress((void**)&p_Wf,   g_Wf);
    cudaGetSymbolAddress((void**)&p_Wb,   g_Wb);
    cudaGetSymbolAddress((void**)&p_bf,   g_bf);
    cudaGetSymbolAddress((void**)&p_bb,   g_bb);
    cudaGetSymbolAddress((void**)&p_Pf,   g_Pf);
    cudaGetSymbolAddress((void**)&p_Pb,   g_Pb);
    cudaGetSymbolAddress((void**)&p_S,    g_S);
    cudaGetSymbolAddress((void**)&p_Yg,   g_Yg);

    prep_pack<<<96, 256>>>(WBf, WCf, WDf, WBb, WCb, WDb, Wi,
                           bBf, bCf, bDf, bBb, bCb, bDb, bi, A_log);
    ln_kernel<<<M_/8, 256>>>(tokens, norm_g, norm_b);

    // x = t@Wx + bx ; gate = sigmoid(silu(t@Wz + bz))
    sgemm<D_, E_, EPI_PLAIN><<<dim3(E_/64, M_/64), 256>>>(p_t, nullptr, Wx, bx, 1.f, nullptr, p_x);
    sgemm<D_, E_, EPI_GATE ><<<dim3(E_/64, M_/64), 256>>>(p_t, nullptr, Wz, bz, 1.f, nullptr, p_gate);

    conv_kernel<<<(M_*E_)/256, 256>>>(convf_w, convf_b, convb_w, convb_b);

    // packed projections: P = xc @ [WB|WC|WD|Wi] + [bB|bC|bD|bi]
    sgemm<E_, 64, EPI_PLAIN><<<dim3(1, M_/64), 256>>>(p_xcf, nullptr, p_Wf, p_bf, 1.f, nullptr, p_Pf);
    sgemm<E_, 64, EPI_PLAIN><<<dim3(1, M_/64), 256>>>(p_xcb, nullptr, p_Wb, p_bb, 1.f, nullptr, p_Pb);

    ssm_prep<<<(2*M_*N_)/256, 256>>>();
    scan_kernel<<<64, 32>>>();

    // Yg = ((Sf+Sb) @ Wr + 2*br) * gate  (Wr/br shared across directions)
    sgemm<N_, E_, EPI_MUL><<<dim3(E_/64, M_/64), 256>>>(p_S, p_S + M_*N_, Wr, br, 2.f, p_gate, p_Yg);
    // out = tokens + Yg @ Wo + bo
    sgemm<E_, D_, EPI_ADD><<<dim3(D_/64, M_/64), 256>>>(p_Yg, nullptr, Wo, bo, 1.f, tokens, (float*)d_out);
}

// round 7
// speedup vs baseline: 1.1591x; 1.1591x over previous
#include <cuda_runtime.h>
#include <math.h>

#define B_ 32
#define J_ 1024
#define D_ 192
#define E_ 384
#define N_ 16
#define M_ (B_*J_)   // 32768 rows

// ---------------- scratch (static __device__, no runtime alloc) ----------------
__device__ __align__(16) float g_t   [M_*D_];
__device__ __align__(16) float g_x   [M_*E_];
__device__ __align__(16) float g_gate[M_*E_];
__device__ __align__(16) float g_Ab  [2*M_*N_];
__device__ __align__(16) float g_Bu  [2*M_*N_];
__device__ __align__(16) float g_Ct  [2*M_*N_];
__device__ __align__(16) float g_S   [2*M_*N_];
__device__ __align__(16) float g_Yg  [M_*E_];
__device__ __align__(16) float g_Wf  [E_*64];
__device__ __align__(16) float g_Wb  [E_*64];
__device__ __align__(16) float g_bf  [64];
__device__ __align__(16) float g_bb  [64];
__device__ __align__(16) float g_Aneg[N_];

__device__ __forceinline__ float softplusf(float x) {
    return x > 20.f ? x : log1pf(expf(x));
}

// ---- pack weights interleaved: col c = 4*n + {B,C,D,u}; A = -softplus(A_log) ----
__global__ void prep_pack(const float* __restrict__ WBf, const float* __restrict__ WCf,
                          const float* __restrict__ WDf, const float* __restrict__ WBb,
                          const float* __restrict__ WCb, const float* __restrict__ WDb,
                          const float* __restrict__ Wi, const float* __restrict__ A_log) {
    int i = blockIdx.x * blockDim.x + threadIdx.x;
    if (i < E_*64) {
        int e = i >> 6, c = i & 63;
        int n = c >> 2, q = c & 3;
        const float* sf = (q == 0) ? WBf : (q == 1) ? WCf : (q == 2) ? WDf : Wi;
        const float* sb = (q == 0) ? WBb : (q == 1) ? WCb : (q == 2) ? WDb : Wi;
        g_Wf[i] = sf[e*N_ + n];
        g_Wb[i] = sb[e*N_ + n];
    }
    if (i < N_) g_Aneg[i] = -softplusf(A_log[i]);
}

// ---- fold conv bias into projection bias: b_eff = b + cb @ Wpack (exact) --------
__global__ void prep_bias(const float* __restrict__ bBf, const float* __restrict__ bCf,
                          const float* __restrict__ bDf, const float* __restrict__ bBb,
                          const float* __restrict__ bCb, const float* __restrict__ bDb,
                          const float* __restrict__ bi,
                          const float* __restrict__ cbf, const float* __restrict__ cbb) {
    int t = threadIdx.x;             // 128 threads: dir x 64 cols
    int dir = t >> 6, c = t & 63;
    int n = c >> 2, q = c & 3;
    const float* bs = dir ? ((q==0)?bBb:(q==1)?bCb:(q==2)?bDb:bi)
                          : ((q==0)?bBf:(q==1)?bCf:(q==2)?bDf:bi);
    const float* Wp = dir ? g_Wb : g_Wf;
    const float* cb = dir ? cbb  : cbf;
    float s = bs[n];
    for (int e = 0; e < E_; e++) s = fmaf(cb[e], Wp[e*64 + c], s);
    (dir ? g_bb : g_bf)[c] = s;
}

// ---------------- LayerNorm: one warp per row ------------------------------------
__global__ void ln_kernel(const float* __restrict__ tok, const float* __restrict__ gw,
                          const float* __restrict__ gb) {
    int warp = (blockIdx.x * blockDim.x + threadIdx.x) >> 5;
    int lane = threadIdx.x & 31;
    if (warp >= M_) return;
    const float* r = tok + (size_t)warp * D_;
    float v[6];
    float s = 0.f;
#pragma unroll
    for (int i = 0; i < 6; i++) { v[i] = r[lane + i*32]; s += v[i]; }
#pragma unroll
    for (int o = 16; o; o >>= 1) s += __shfl_xor_sync(0xffffffffu, s, o);
    float mu = s * (1.f / D_);
    float q = 0.f;
#pragma unroll
    for (int i = 0; i < 6; i++) { float d = v[i] - mu; q += d * d; }
#pragma unroll
    for (int o = 16; o; o >>= 1) q += __shfl_xor_sync(0xffffffffu, q, o);
    float rs = rsqrtf(q * (1.f / D_) + 1e-5f);
    float* o = g_t + (size_t)warp * D_;
#pragma unroll
    for (int i = 0; i < 6; i++) {
        int c = lane + i*32;
        o[c] = (v[i] - mu) * rs * gw[c] + gb[c];
    }
}

// ---------------- GEMM: BM=128, BN in {64,128}, BK=16, 8x8 microtile --------------
enum { EPI_PLAIN = 0, EPI_GATE = 1, EPI_MUL = 2, EPI_ADD = 3, EPI_SSM = 4 };

template <int KD, int ND, int BN, int EPI, int CONV>
__global__ void __launch_bounds__(16*(BN/8)) gemm_k(
    const float* __restrict__ A, const float* __restrict__ A2,
    const float* __restrict__ W, const float* __restrict__ bias,
    float bscale, const float* __restrict__ aux, float* __restrict__ C,
    const float* __restrict__ cw, int ssm_base)
{
    constexpr int BM = 128, BK = 16;
    constexpr int TX = BN / 8;       // thread cols (16 or 8)
    constexpr int NT = 16 * TX;      // 256 or 128 threads
    constexpr int HN = BN / 2;
    __shared__ float As[2][BK][BM];
    __shared__ float Ws[2][BK][BN];
    __shared__ float cws[CONV ? 3*KD : 4];

    int tid = threadIdx.x;
    int tx = tid % TX, ty = tid / TX;
    int row0 = blockIdx.y * BM, col0 = blockIdx.x * BN;

    if (CONV) {
        for (int i = tid; i < 3*KD; i += NT) cws[i] = cw[i];
        __syncthreads();
    }

    float regA[16];
    float regW[16];

    auto loadA = [&](int k0) {
        int row = row0 + tid;   // only called for tid < 128
        if (CONV == 0) {
#pragma unroll
            for (int q = 0; q < 4; q++) {
                float4 v = *(const float4*)&A[(size_t)row*KD + k0 + q*4];
                if (A2) {
                    float4 v2 = *(const float4*)&A2[(size_t)row*KD + k0 + q*4];
                    v.x += v2.x; v.y += v2.y; v.z += v2.z; v.w += v2.w;
                }
                *(float4*)&regA[q*4] = v;
            }
        } else {
            int j = row & (J_ - 1);
            const float* xr = A + (size_t)row*KD + k0;
            float4 z4 = make_float4(0.f, 0.f, 0.f, 0.f);
#pragma unroll
            for (int q = 0; q < 4; q++) {
                float4 x0 = *(const float4*)&xr[q*4];
                float4 xm = (j > 0)      ? *(const float4*)&xr[q*4 - KD] : z4;
                float4 xp = (j < J_ - 1) ? *(const float4*)&xr[q*4 + KD] : z4;
#pragma unroll
                for (int i = 0; i < 4; i++) {
                    int e = k0 + q*4 + i;
                    float w0 = cws[e*3], w1 = cws[e*3+1], w2 = cws[e*3+2];
                    float a = (&x0.x)[i], m = (&xm.x)[i], p = (&xp.x)[i];
                    regA[q*4+i] = (CONV == 1)
                        ? fmaf(w0, m, fmaf(w1, a, w2 * p))
                        : fmaf(w0, p, fmaf(w1, a, w2 * m));
                }
            }
        }
    };

    auto load_tile = [&](int k0) {
        if (BN == 128) {
            if (tid < 128) {
                loadA(k0);
            } else {
                int t = tid - 128;
                int wk = t >> 3, wn = (t & 7) * 16;
#pragma unroll
                for (int q = 0; q < 4; q++)
                    *(float4*)&regW[q*4] = *(const float4*)&W[(size_t)(k0+wk)*ND + col0 + wn + q*4];
            }
        } else {
            loadA(k0);
            int wk = tid >> 3, wn = (tid & 7) * 8;
            *(float4*)&regW[0] = *(const float4*)&W[(size_t)(k0+wk)*ND + col0 + wn];
            *(float4*)&regW[4] = *(const float4*)&W[(size_t)(k0+wk)*ND + col0 + wn + 4];
        }
    };

    auto store_tile = [&](int buf) {
        if (BN == 128) {
            if (tid < 128) {
#pragma unroll
                for (int k = 0; k < BK; k++) As[buf][k][tid] = regA[k];
            } else {
                int t = tid - 128;
                int wk = t >> 3, wn = (t & 7) * 16;
#pragma unroll
                for (int q = 0; q < 4; q++)
                    *(float4*)&Ws[buf][wk][wn + q*4] = *(float4*)&regW[q*4];
            }
        } else {
#pragma unroll
            for (int k = 0; k < BK; k++) As[buf][k][tid] = regA[k];
            int wk = tid >> 3, wn = (tid & 7) * 8;
            *(float4*)&Ws[buf][wk][wn]     = *(float4*)&regW[0];
            *(float4*)&Ws[buf][wk][wn + 4] = *(float4*)&regW[4];
        }
    };

    float acc[8][8] = {};

    load_tile(0);
    store_tile(0);
    __syncthreads();
    int buf = 0;
    for (int k0 = BK; k0 <= KD; k0 += BK) {
        bool has_next = (k0 < KD);
        if (has_next) load_tile(k0);
#pragma unroll
        for (int kk = 0; kk < BK; kk++) {
            float a[8], b[8];
            *(float4*)&a[0] = *(const float4*)&As[buf][kk][ty*4];
            *(float4*)&a[4] = *(const float4*)&As[buf][kk][64 + ty*4];
            *(float4*)&b[0] = *(const float4*)&Ws[buf][kk][tx*4];
            *(float4*)&b[4] = *(const float4*)&Ws[buf][kk][HN + tx*4];
#pragma unroll
            for (int i = 0; i < 8; i++)
#pragma unroll
                for (int jj = 0; jj < 8; jj++)
                    acc[i][jj] = fmaf(a[i], b[jj], acc[i][jj]);
        }
        if (has_next) {
            store_tile(buf ^ 1);
            __syncthreads();
            buf ^= 1;
        }
    }

    // -------- epilogue --------
#pragma unroll
    for (int rr = 0; rr < 8; rr++) {
        int row = row0 + ty*4 + (rr & 3) + ((rr >> 2) * 64);
        if (EPI == EPI_SSM) {
#pragma unroll
            for (int h = 0; h < 2; h++) {
                int n = h*8 + tx;
                float vB = acc[rr][h*4+0] + bias[h*32 + tx*4 + 0];
                float vC = acc[rr][h*4+1] + bias[h*32 + tx*4 + 1];
                float vD = acc[rr][h*4+2] + bias[h*32 + tx*4 + 2];
                float vu = acc[rr][h*4+3] + bias[h*32 + tx*4 + 3];
                float Dt = softplusf(vD);
                float Aa = g_Aneg[n];
                float ab = __expf(Dt * Aa);
                float bu = (ab - 1.f) / (Aa + 1e-6f) * vB * vu;
                int idx = ssm_base + row*N_ + n;
                g_Ab[idx] = ab;
                g_Bu[idx] = bu;
                g_Ct[idx] = vC;
            }
        } else {
#pragma unroll
            for (int h = 0; h < 2; h++) {
                int col = col0 + h*HN + tx*4;
                size_t co = (size_t)row * ND + col;
                float4 xv;
                if (EPI == EPI_MUL || EPI == EPI_ADD) xv = *(const float4*)&aux[co];
                float o[4];
#pragma unroll
                for (int q = 0; q < 4; q++) {
                    float v = acc[rr][h*4+q] + bscale * bias[col + q];
                    if (EPI == EPI_GATE) {
                        float sg = 1.f / (1.f + __expf(-v));
                        float si = v * sg;
                        v = 1.f / (1.f + __expf(-si));
                    } else if (EPI == EPI_MUL) {
                        v *= (&xv.x)[q];
                    } else if (EPI == EPI_ADD) {
                        v += (&xv.x)[q];
                    }
                    o[q] = v;
                }
                *(float4*)&C[co] = *(float4*)o;
            }
        }
    }
}

// ------- sequential scan: one warp per (dir, b); lanes = n; pipelined loads -------
__global__ void scan_kernel() {
    int wg   = blockIdx.x;
    int lane = threadIdx.x;
    if (lane >= N_) return;
    int dir = wg & 1, b = wg >> 1;
    int base = dir * M_ * N_ + b * J_ * N_ + lane;
    int step = dir ? -N_ : N_;
    int idx  = dir ? (base + (J_ - 1) * N_) : base;

    const int U = 4;
    float ab[U], bu[U], ct[U];
    // prologue: prefetch first group
#pragma unroll
    for (int u = 0; u < U; u++) {
        int i2 = idx + u * step;
        ab[u] = g_Ab[i2]; bu[u] = g_Bu[i2]; ct[u] = g_Ct[i2];
    }
    float h = 0.f;
    for (int j0 = 0; j0 < J_; j0 += U) {
        float nab[U], nbu[U], nct[U];
        if (j0 + U < J_) {
#pragma unroll
            for (int u = 0; u < U; u++) {
                int i2 = idx + (U + u) * step;
                nab[u] = g_Ab[i2]; nbu[u] = g_Bu[i2]; nct[u] = g_Ct[i2];
            }
        }
#pragma unroll
        for (int u = 0; u < U; u++) {
            h = fmaf(ab[u], h, bu[u]);
            g_S[idx + u * step] = h * ct[u];
        }
#pragma unroll
        for (int u = 0; u < U; u++) { ab[u] = nab[u]; bu[u] = nbu[u]; ct[u] = nct[u]; }
        idx += U * step;
    }
}

// ---------------- launch ----------------------------------------------------------
extern "C" void kernel_launch(void* const* d_in, const int* in_sizes, int n_in,
                              void* d_out, int out_size) {
    const float* tokens  = (const float*)d_in[0];
    const float* norm_g  = (const float*)d_in[1];
    const float* norm_b  = (const float*)d_in[2];
    const float* Wx      = (const float*)d_in[3];
    const float* bx      = (const float*)d_in[4];
    const float* Wz      = (const float*)d_in[5];
    const float* bz      = (const float*)d_in[6];
    const float* convf_w = (const float*)d_in[7];
    const float* convf_b = (const float*)d_in[8];
    const float* convb_w = (const float*)d_in[9];
    const float* convb_b = (const float*)d_in[10];
    const float* WBf = (const float*)d_in[11];
    const float* bBf = (const float*)d_in[12];
    const float* WCf = (const float*)d_in[13];
    const float* bCf = (const float*)d_in[14];
    const float* WDf = (const float*)d_in[15];
    const float* bDf = (const float*)d_in[16];
    const float* WBb = (const float*)d_in[17];
    const float* bBb = (const float*)d_in[18];
    const float* WCb = (const float*)d_in[19];
    const float* bCb = (const float*)d_in[20];
    const float* WDb = (const float*)d_in[21];
    const float* bDb = (const float*)d_in[22];
    const float* A_log = (const float*)d_in[23];
    const float* Wi  = (const float*)d_in[24];
    const float* bi  = (const float*)d_in[25];
    const float* Wr  = (const float*)d_in[26];
    const float* br  = (const float*)d_in[27];
    const float* Wo  = (const float*)d_in[28];
    const float* bo  = (const float*)d_in[29];

    float *p_t, *p_x, *p_gate, *p_Wf, *p_Wb, *p_bf, *p_bb, *p_S, *p_Yg;
    cudaGetSymbolAddress((void**)&p_t,    g_t);
    cudaGetSymbolAddress((void**)&p_x,    g_x);
    cudaGetSymbolAddress((void**)&p_gate, g_gate);
    cudaGetSymbolAddress((void**)&p_Wf,   g_Wf);
    cudaGetSymbolAddress((void**)&p_Wb,   g_Wb);
    cudaGetSymbolAddress((void**)&p_bf,   g_bf);
    cudaGetSymbolAddress((void**)&p_bb,   g_bb);
    cudaGetSymbolAddress((void**)&p_S,    g_S);
    cudaGetSymbolAddress((void**)&p_Yg,   g_Yg);

    prep_pack<<<96, 256>>>(WBf, WCf, WDf, WBb, WCb, WDb, Wi, A_log);
    prep_bias<<<1, 128>>>(bBf, bCf, bDf, bBb, bCb, bDb, bi, convf_b, convb_b);
    ln_kernel<<<M_/8, 256>>>(tokens, norm_g, norm_b);

    // x = t@Wx + bx ; gate = sigmoid(silu(t@Wz + bz))
    gemm_k<D_, E_, 128, EPI_PLAIN, 0><<<dim3(E_/128, M_/128), 256>>>(
        p_t, nullptr, Wx, bx, 1.f, nullptr, p_x, nullptr, 0);
    gemm_k<D_, E_, 128, EPI_GATE, 0><<<dim3(E_/128, M_/128), 256>>>(
        p_t, nullptr, Wz, bz, 1.f, nullptr, p_gate, nullptr, 0);

    // fused conv + packed projections + ZOH discretization (per direction)
    gemm_k<E_, 64, 64, EPI_SSM, 1><<<dim3(1, M_/128), 128>>>(
        p_x, nullptr, p_Wf, p_bf, 1.f, nullptr, nullptr, convf_w, 0);
    gemm_k<E_, 64, 64, EPI_SSM, 2><<<dim3(1, M_/128), 128>>>(
        p_x, nullptr, p_Wb, p_bb, 1.f, nullptr, nullptr, convb_w, M_*N_);

    scan_kernel<<<64, 32>>>();

    // Yg = ((Sf+Sb) @ Wr + 2*br) * gate
    gemm_k<N_, E_, 128, EPI_MUL, 0><<<dim3(E_/128, M_/128), 256>>>(
        p_S, p_S + M_*N_, Wr, br, 2.f, p_gate, p_Yg, nullptr, 0);
    // out = tokens + Yg @ Wo + bo
    gemm_k<E_, D_, 64, EPI_ADD, 0><<<dim3(D_/64, M_/128), 128>>>(
        p_Yg, nullptr, Wo, bo, 1.f, tokens, (float*)d_out, nullptr, 0);
}

// round 11
// speedup vs baseline: 1.2726x; 1.0979x over previous
#include <cuda_runtime.h>
#include <math.h>

#define B_ 32
#define J_ 1024
#define D_ 192
#define E_ 384
#define N_ 16
#define M_ (B_*J_)   // 32768 rows

// ---------------- scratch (static __device__, no runtime alloc) ----------------
__device__ __align__(16) float g_t   [M_*D_];
__device__ __align__(16) float g_x   [M_*E_];
__device__ __align__(16) float g_gate[M_*E_];
__device__ __align__(16) float g_Ab  [2*M_*N_];
__device__ __align__(16) float g_Bu  [2*M_*N_];
__device__ __align__(16) float g_Ct  [2*M_*N_];
__device__ __align__(16) float g_S   [2*M_*N_];
__device__ __align__(16) float g_Yg  [M_*E_];
__device__ __align__(16) float g_Wf  [E_*64];
__device__ __align__(16) float g_Wb  [E_*64];
__device__ __align__(16) float g_bf  [64];
__device__ __align__(16) float g_bb  [64];
__device__ __align__(16) float g_Aneg[N_];

__device__ __forceinline__ float softplusf(float x) {
    return x > 20.f ? x : log1pf(expf(x));
}

// ---- pack weights interleaved: col c = 4*n + {B,C,D,u}; A = -softplus(A_log) ----
__global__ void prep_pack(const float* __restrict__ WBf, const float* __restrict__ WCf,
                          const float* __restrict__ WDf, const float* __restrict__ WBb,
                          const float* __restrict__ WCb, const float* __restrict__ WDb,
                          const float* __restrict__ Wi, const float* __restrict__ A_log) {
    int i = blockIdx.x * blockDim.x + threadIdx.x;
    if (i < E_*64) {
        int e = i >> 6, c = i & 63;
        int n = c >> 2, q = c & 3;
        const float* sf = (q == 0) ? WBf : (q == 1) ? WCf : (q == 2) ? WDf : Wi;
        const float* sb = (q == 0) ? WBb : (q == 1) ? WCb : (q == 2) ? WDb : Wi;
        g_Wf[i] = sf[e*N_ + n];
        g_Wb[i] = sb[e*N_ + n];
    }
    if (i < N_) g_Aneg[i] = -softplusf(A_log[i]);
}

// ---- fold conv bias into projection bias: b_eff = b + cb @ Wpack (exact) --------
__global__ void prep_bias(const float* __restrict__ bBf, const float* __restrict__ bCf,
                          const float* __restrict__ bDf, const float* __restrict__ bBb,
                          const float* __restrict__ bCb, const float* __restrict__ bDb,
                          const float* __restrict__ bi,
                          const float* __restrict__ cbf, const float* __restrict__ cbb) {
    int t = threadIdx.x;             // 128 threads: dir x 64 cols
    int dir = t >> 6, c = t & 63;
    int n = c >> 2, q = c & 3;
    const float* bs = dir ? ((q==0)?bBb:(q==1)?bCb:(q==2)?bDb:bi)
                          : ((q==0)?bBf:(q==1)?bCf:(q==2)?bDf:bi);
    const float* Wp = dir ? g_Wb : g_Wf;
    const float* cb = dir ? cbb  : cbf;
    float s = bs[n];
    for (int e = 0; e < E_; e++) s = fmaf(cb[e], Wp[e*64 + c], s);
    (dir ? g_bb : g_bf)[c] = s;
}

// ---------------- LayerNorm: one warp per row ------------------------------------
__global__ void ln_kernel(const float* __restrict__ tok, const float* __restrict__ gw,
                          const float* __restrict__ gb) {
    int warp = (blockIdx.x * blockDim.x + threadIdx.x) >> 5;
    int lane = threadIdx.x & 31;
    if (warp >= M_) return;
    const float* r = tok + (size_t)warp * D_;
    float v[6];
    float s = 0.f;
#pragma unroll
    for (int i = 0; i < 6; i++) { v[i] = r[lane + i*32]; s += v[i]; }
#pragma unroll
    for (int o = 16; o; o >>= 1) s += __shfl_xor_sync(0xffffffffu, s, o);
    float mu = s * (1.f / D_);
    float q = 0.f;
#pragma unroll
    for (int i = 0; i < 6; i++) { float d = v[i] - mu; q += d * d; }
#pragma unroll
    for (int o = 16; o; o >>= 1) q += __shfl_xor_sync(0xffffffffu, q, o);
    float rs = rsqrtf(q * (1.f / D_) + 1e-5f);
    float* o = g_t + (size_t)warp * D_;
#pragma unroll
    for (int i = 0; i < 6; i++) {
        int c = lane + i*32;
        o[c] = (v[i] - mu) * rs * gw[c] + gb[c];
    }
}

// ---------------- GEMM: BM=128, BN in {64,128}, BK=16, 8x8 microtile --------------
// Inner product via packed fma.rn.f32x2 (FFMA2): acc columns paired (j, j+1).
enum { EPI_PLAIN = 0, EPI_GATE = 1, EPI_MUL = 2, EPI_ADD = 3, EPI_SSM = 4 };

template <int KD, int ND, int BN, int EPI, int CONV>
__global__ void __launch_bounds__(16*(BN/8)) gemm_k(
    const float* __restrict__ A, const float* __restrict__ A2,
    const float* __restrict__ W, const float* __restrict__ bias,
    float bscale, const float* __restrict__ aux, float* __restrict__ C,
    const float* __restrict__ cw, int ssm_base)
{
    constexpr int BM = 128, BK = 16;
    constexpr int TX = BN / 8;       // thread cols (16 or 8)
    constexpr int NT = 16 * TX;      // 256 or 128 threads
    constexpr int HN = BN / 2;
    __shared__ float As[2][BK][BM];
    __shared__ float Ws[2][BK][BN];
    __shared__ float cws[CONV ? 3*KD : 4];

    int tid = threadIdx.x;
    int tx = tid % TX, ty = tid / TX;
    int row0 = blockIdx.y * BM, col0 = blockIdx.x * BN;

    if (CONV) {
        for (int i = tid; i < 3*KD; i += NT) cws[i] = cw[i];
        __syncthreads();
    }

    float regA[16];
    float regW[16];

    auto loadA = [&](int k0) {
        int row = row0 + tid;   // only called for tid < 128
        if (CONV == 0) {
#pragma unroll
            for (int q = 0; q < 4; q++) {
                float4 v = *(const float4*)&A[(size_t)row*KD + k0 + q*4];
                if (A2) {
                    float4 v2 = *(const float4*)&A2[(size_t)row*KD + k0 + q*4];
                    v.x += v2.x; v.y += v2.y; v.z += v2.z; v.w += v2.w;
                }
                *(float4*)&regA[q*4] = v;
            }
        } else {
            int j = row & (J_ - 1);
            const float* xr = A + (size_t)row*KD + k0;
            float4 z4 = make_float4(0.f, 0.f, 0.f, 0.f);
#pragma unroll
            for (int q = 0; q < 4; q++) {
                float4 x0 = *(const float4*)&xr[q*4];
                float4 xm = (j > 0)      ? *(const float4*)&xr[q*4 - KD] : z4;
                float4 xp = (j < J_ - 1) ? *(const float4*)&xr[q*4 + KD] : z4;
#pragma unroll
                for (int i = 0; i < 4; i++) {
                    int e = k0 + q*4 + i;
                    float w0 = cws[e*3], w1 = cws[e*3+1], w2 = cws[e*3+2];
                    float a = (&x0.x)[i], m = (&xm.x)[i], p = (&xp.x)[i];
                    regA[q*4+i] = (CONV == 1)
                        ? fmaf(w0, m, fmaf(w1, a, w2 * p))
                        : fmaf(w0, p, fmaf(w1, a, w2 * m));
                }
            }
        }
    };

    auto load_tile = [&](int k0) {
        if (BN == 128) {
            if (tid < 128) {
                loadA(k0);
            } else {
                int t = tid - 128;
                int wk = t >> 3, wn = (t & 7) * 16;
#pragma unroll
                for (int q = 0; q < 4; q++)
                    *(float4*)&regW[q*4] = *(const float4*)&W[(size_t)(k0+wk)*ND + col0 + wn + q*4];
            }
        } else {
            loadA(k0);
            int wk = tid >> 3, wn = (tid & 7) * 8;
            *(float4*)&regW[0] = *(const float4*)&W[(size_t)(k0+wk)*ND + col0 + wn];
            *(float4*)&regW[4] = *(const float4*)&W[(size_t)(k0+wk)*ND + col0 + wn + 4];
        }
    };

    auto store_tile = [&](int buf) {
        if (BN == 128) {
            if (tid < 128) {
#pragma unroll
                for (int k = 0; k < BK; k++) As[buf][k][tid] = regA[k];
            } else {
                int t = tid - 128;
                int wk = t >> 3, wn = (t & 7) * 16;
#pragma unroll
                for (int q = 0; q < 4; q++)
                    *(float4*)&Ws[buf][wk][wn + q*4] = *(float4*)&regW[q*4];
            }
        } else {
#pragma unroll
            for (int k = 0; k < BK; k++) As[buf][k][tid] = regA[k];
            int wk = tid >> 3, wn = (tid & 7) * 8;
            *(float4*)&Ws[buf][wk][wn]     = *(float4*)&regW[0];
            *(float4*)&Ws[buf][wk][wn + 4] = *(float4*)&regW[4];
        }
    };

    // packed accumulators: accp[i][jp] holds columns (2*jp, 2*jp+1) of logical row i
    unsigned long long accp[8][4] = {};

    load_tile(0);
    store_tile(0);
    __syncthreads();
    int buf = 0;
    for (int k0 = BK; k0 <= KD; k0 += BK) {
        bool has_next = (k0 < KD);
        if (has_next) load_tile(k0);
#pragma unroll
        for (int kk = 0; kk < BK; kk++) {
            float a[8];
            *(float4*)&a[0] = *(const float4*)&As[buf][kk][ty*4];
            *(float4*)&a[4] = *(const float4*)&As[buf][kk][64 + ty*4];
            // b pairs load pre-packed from shared (16B aligned)
            ulonglong2 b01 = *(const ulonglong2*)&Ws[buf][kk][tx*4];
            ulonglong2 b23 = *(const ulonglong2*)&Ws[buf][kk][HN + tx*4];
            unsigned long long bp[4];
            bp[0] = b01.x; bp[1] = b01.y; bp[2] = b23.x; bp[3] = b23.y;
            unsigned long long ad[8];
#pragma unroll
            for (int i = 0; i < 8; i++) {
                unsigned int u = __float_as_uint(a[i]);
                asm("mov.b64 %0, {%1, %2};" : "=l"(ad[i]) : "r"(u), "r"(u));
            }
#pragma unroll
            for (int i = 0; i < 8; i++)
#pragma unroll
                for (int jp = 0; jp < 4; jp++)
                    asm("fma.rn.f32x2 %0, %1, %2, %0;"
                        : "+l"(accp[i][jp]) : "l"(ad[i]), "l"(bp[jp]));
        }
        if (has_next) {
            store_tile(buf ^ 1);
            __syncthreads();
            buf ^= 1;
        }
    }

    // -------- epilogue --------
#pragma unroll
    for (int rr = 0; rr < 8; rr++) {
        int row = row0 + ty*4 + (rr & 3) + ((rr >> 2) * 64);
        float accf[8];
#pragma unroll
        for (int jp = 0; jp < 4; jp++) {
            unsigned int r0, r1;
            asm("mov.b64 {%0, %1}, %2;" : "=r"(r0), "=r"(r1) : "l"(accp[rr][jp]));
            accf[2*jp]   = __uint_as_float(r0);
            accf[2*jp+1] = __uint_as_float(r1);
        }
        if (EPI == EPI_SSM) {
#pragma unroll
            for (int h = 0; h < 2; h++) {
                int n = h*8 + tx;
                float vB = accf[h*4+0] + bias[h*32 + tx*4 + 0];
                float vC = accf[h*4+1] + bias[h*32 + tx*4 + 1];
                float vD = accf[h*4+2] + bias[h*32 + tx*4 + 2];
                float vu = accf[h*4+3] + bias[h*32 + tx*4 + 3];
                float Dt = softplusf(vD);
                float Aa = g_Aneg[n];
                float ab = __expf(Dt * Aa);
                float bu = (ab - 1.f) / (Aa + 1e-6f) * vB * vu;
                int idx = ssm_base + row*N_ + n;
                g_Ab[idx] = ab;
                g_Bu[idx] = bu;
                g_Ct[idx] = vC;
            }
        } else {
#pragma unroll
            for (int h = 0; h < 2; h++) {
                int col = col0 + h*HN + tx*4;
                size_t co = (size_t)row * ND + col;
                float4 xv;
                if (EPI == EPI_MUL || EPI == EPI_ADD) xv = *(const float4*)&aux[co];
                float o[4];
#pragma unroll
                for (int q = 0; q < 4; q++) {
                    float v = accf[h*4+q] + bscale * bias[col + q];
                    if (EPI == EPI_GATE) {
                        float sg = 1.f / (1.f + __expf(-v));
                        float si = v * sg;
                        v = 1.f / (1.f + __expf(-si));
                    } else if (EPI == EPI_MUL) {
                        v *= (&xv.x)[q];
                    } else if (EPI == EPI_ADD) {
                        v += (&xv.x)[q];
                    }
                    o[q] = v;
                }
                *(float4*)&C[co] = *(float4*)o;
            }
        }
    }
}

// ------- sequential scan: one warp per (dir, b); lanes = n; pipelined loads -------
__global__ void scan_kernel() {
    int wg   = blockIdx.x;
    int lane = threadIdx.x;
    if (lane >= N_) return;
    int dir = wg & 1, b = wg >> 1;
    int base = dir * M_ * N_ + b * J_ * N_ + lane;
    int step = dir ? -N_ : N_;
    int idx  = dir ? (base + (J_ - 1) * N_) : base;

    const int U = 4;
    float ab[U], bu[U], ct[U];
#pragma unroll
    for (int u = 0; u < U; u++) {
        int i2 = idx + u * step;
        ab[u] = g_Ab[i2]; bu[u] = g_Bu[i2]; ct[u] = g_Ct[i2];
    }
    float h = 0.f;
    for (int j0 = 0; j0 < J_; j0 += U) {
        float nab[U], nbu[U], nct[U];
        if (j0 + U < J_) {
#pragma unroll
            for (int u = 0; u < U; u++) {
                int i2 = idx + (U + u) * step;
                nab[u] = g_Ab[i2]; nbu[u] = g_Bu[i2]; nct[u] = g_Ct[i2];
            }
        }
#pragma unroll
        for (int u = 0; u < U; u++) {
            h = fmaf(ab[u], h, bu[u]);
            g_S[idx + u * step] = h * ct[u];
        }
#pragma unroll
        for (int u = 0; u < U; u++) { ab[u] = nab[u]; bu[u] = nbu[u]; ct[u] = nct[u]; }
        idx += U * step;
    }
}

// ---------------- launch ----------------------------------------------------------
extern "C" void kernel_launch(void* const* d_in, const int* in_sizes, int n_in,
                              void* d_out, int out_size) {
    const float* tokens  = (const float*)d_in[0];
    const float* norm_g  = (const float*)d_in[1];
    const float* norm_b  = (const float*)d_in[2];
    const float* Wx      = (const float*)d_in[3];
    const float* bx      = (const float*)d_in[4];
    const float* Wz      = (const float*)d_in[5];
    const float* bz      = (const float*)d_in[6];
    const float* convf_w = (const float*)d_in[7];
    const float* convf_b = (const float*)d_in[8];
    const float* convb_w = (const float*)d_in[9];
    const float* convb_b = (const float*)d_in[10];
    const float* WBf = (const float*)d_in[11];
    const float* bBf = (const float*)d_in[12];
    const float* WCf = (const float*)d_in[13];
    const float* bCf = (const float*)d_in[14];
    const float* WDf = (const float*)d_in[15];
    const float* bDf = (const float*)d_in[16];
    const float* WBb = (const float*)d_in[17];
    const float* bBb = (const float*)d_in[18];
    const float* WCb = (const float*)d_in[19];
    const float* bCb = (const float*)d_in[20];
    const float* WDb = (const float*)d_in[21];
    const float* bDb = (const float*)d_in[22];
    const float* A_log = (const float*)d_in[23];
    const float* Wi  = (const float*)d_in[24];
    const float* bi  = (const float*)d_in[25];
    const float* Wr  = (const float*)d_in[26];
    const float* br  = (const float*)d_in[27];
    const float* Wo  = (const float*)d_in[28];
    const float* bo  = (const float*)d_in[29];

    float *p_t, *p_x, *p_gate, *p_Wf, *p_Wb, *p_bf, *p_bb, *p_S, *p_Yg;
    cudaGetSymbolAddress((void**)&p_t,    g_t);
    cudaGetSymbolAddress((void**)&p_x,    g_x);
    cudaGetSymbolAddress((void**)&p_gate, g_gate);
    cudaGetSymbolAddress((void**)&p_Wf,   g_Wf);
    cudaGetSymbolAddress((void**)&p_Wb,   g_Wb);
    cudaGetSymbolAddress((void**)&p_bf,   g_bf);
    cudaGetSymbolAddress((void**)&p_bb,   g_bb);
    cudaGetSymbolAddress((void**)&p_S,    g_S);
    cudaGetSymbolAddress((void**)&p_Yg,   g_Yg);

    prep_pack<<<96, 256>>>(WBf, WCf, WDf, WBb, WCb, WDb, Wi, A_log);
    prep_bias<<<1, 128>>>(bBf, bCf, bDf, bBb, bCb, bDb, bi, convf_b, convb_b);
    ln_kernel<<<M_/8, 256>>>(tokens, norm_g, norm_b);

    // x = t@Wx + bx ; gate = sigmoid(silu(t@Wz + bz))
    gemm_k<D_, E_, 128, EPI_PLAIN, 0><<<dim3(E_/128, M_/128), 256>>>(
        p_t, nullptr, Wx, bx, 1.f, nullptr, p_x, nullptr, 0);
    gemm_k<D_, E_, 128, EPI_GATE, 0><<<dim3(E_/128, M_/128), 256>>>(
        p_t, nullptr, Wz, bz, 1.f, nullptr, p_gate, nullptr, 0);

    // fused conv + packed projections + ZOH discretization (per direction)
    gemm_k<E_, 64, 64, EPI_SSM, 1><<<dim3(1, M_/128), 128>>>(
        p_x, nullptr, p_Wf, p_bf, 1.f, nullptr, nullptr, convf_w, 0);
    gemm_k<E_, 64, 64, EPI_SSM, 2><<<dim3(1, M_/128), 128>>>(
        p_x, nullptr, p_Wb, p_bb, 1.f, nullptr, nullptr, convb_w, M_*N_);

    scan_kernel<<<64, 32>>>();

    // Yg = ((Sf+Sb) @ Wr + 2*br) * gate
    gemm_k<N_, E_, 128, EPI_MUL, 0><<<dim3(E_/128, M_/128), 256>>>(
        p_S, p_S + M_*N_, Wr, br, 2.f, p_gate, p_Yg, nullptr, 0);
    // out = tokens + Yg @ Wo + bo
    gemm_k<E_, D_, 64, EPI_ADD, 0><<<dim3(D_/64, M_/128), 128>>>(
        p_Yg, nullptr, Wo, bo, 1.f, tokens, (float*)d_out, nullptr, 0);
}